// round 13
// baseline (speedup 1.0000x reference)
#include <cuda_runtime.h>
#include <cuda_fp16.h>

// Problem constants
#define BB 4
#define CC 64
#define NN 4096
#define DD 8      // q/k dim = C/8
#define MR 80     // v rows padded: 64 v + 1 ones + 15 zeros
#define BM 32     // m-columns per CTA (attn)
#define NSPLIT 2  // split-K over n
#define NHALF (NN / NSPLIT)     // 2048
#define BN 64     // n tile
#define NT (NHALF / BN)         // 32 tiles per CTA
#define PCOLS 32  // proj: columns per CTA

// Scratch (allocation-free: __device__ globals)
__device__ __half g_wh[80 * 64];             // fused fp16 weights; k rows pre-scaled by log2(e)
__device__ __half g_qt[BB * NN * DD];        // [b][n][8]
__device__ __half g_kt[BB * NN * DD];        // [b][m][8]  (already * log2e)
__device__ __half g_vp[BB * NN * MR];        // [b][n][r]: r<64 v, r=64 ones, 65..79 zero
__device__ float  g_part[NSPLIT * BB * 65 * NN];  // partial O (+denom row 64)

// ---------------------------------------------------------------------------
// helpers
// ---------------------------------------------------------------------------
__device__ __forceinline__ unsigned smem_u32(const void* p) {
    return (unsigned)__cvta_generic_to_shared(p);
}
__device__ __forceinline__ void cpa16(void* dst, const void* src) {
    asm volatile("cp.async.cg.shared.global [%0], [%1], 16;\n"
                 :: "r"(smem_u32(dst)), "l"(src));
}
__device__ __forceinline__ void cpa_commit() {
    asm volatile("cp.async.commit_group;\n");
}
template <int N>
__device__ __forceinline__ void cpa_wait() {
    asm volatile("cp.async.wait_group %0;\n" :: "n"(N));
}
__device__ __forceinline__ void ldm_x2(unsigned& r0, unsigned& r1, unsigned addr) {
    asm volatile("ldmatrix.sync.aligned.m8n8.x2.shared.b16 {%0,%1}, [%2];\n"
                 : "=r"(r0), "=r"(r1) : "r"(addr));
}
__device__ __forceinline__ void ldm_x2_t(unsigned& r0, unsigned& r1, unsigned addr) {
    asm volatile("ldmatrix.sync.aligned.m8n8.x2.trans.shared.b16 {%0,%1}, [%2];\n"
                 : "=r"(r0), "=r"(r1) : "r"(addr));
}
__device__ __forceinline__ void ldm_x4(unsigned& r0, unsigned& r1, unsigned& r2, unsigned& r3, unsigned addr) {
    asm volatile("ldmatrix.sync.aligned.m8n8.x4.shared.b16 {%0,%1,%2,%3}, [%4];\n"
                 : "=r"(r0), "=r"(r1), "=r"(r2), "=r"(r3) : "r"(addr));
}
__device__ __forceinline__ void ldm_x4_t(unsigned& r0, unsigned& r1, unsigned& r2, unsigned& r3, unsigned addr) {
    asm volatile("ldmatrix.sync.aligned.m8n8.x4.trans.shared.b16 {%0,%1,%2,%3}, [%4];\n"
                 : "=r"(r0), "=r"(r1), "=r"(r2), "=r"(r3) : "r"(addr));
}
// f16-accumulator S-MMA: C fragment {c0,c1} is exactly the exp-input pair.
__device__ __forceinline__ void mma_k8_f16(unsigned& c0, unsigned& c1,
                                           unsigned a0, unsigned a1, unsigned b0) {
    asm volatile(
        "mma.sync.aligned.m16n8k8.row.col.f16.f16.f16.f16 "
        "{%0,%1}, {%2,%3}, {%4}, {%0,%1};\n"
        : "+r"(c0), "+r"(c1)
        : "r"(a0), "r"(a1), "r"(b0));
}
__device__ __forceinline__ void mma_k16(float* c, unsigned a0, unsigned a1, unsigned a2, unsigned a3,
                                        unsigned b0, unsigned b1) {
    asm volatile(
        "mma.sync.aligned.m16n8k16.row.col.f32.f16.f16.f32 "
        "{%0,%1,%2,%3}, {%4,%5,%6,%7}, {%8,%9}, {%0,%1,%2,%3};\n"
        : "+f"(c[0]), "+f"(c[1]), "+f"(c[2]), "+f"(c[3])
        : "r"(a0), "r"(a1), "r"(a2), "r"(a3), "r"(b0), "r"(b1));
}

// ---------------------------------------------------------------------------
// One-shot weight fuse+convert: g_wh[80][64] fp16.
// rows 0..7 = Wq, 8..15 = Wk * log2(e), 16..79 = Wv.
// ---------------------------------------------------------------------------
__global__ __launch_bounds__(128) void wconv_kernel(
    const float* __restrict__ Wq,
    const float* __restrict__ Wk,
    const float* __restrict__ Wv)
{
    int idx = blockIdx.x * 128 + threadIdx.x;    // 0..1279 float4
    if (idx >= 1280) return;
    int r = idx >> 4, s = idx & 15;
    const float* src;
    float scale = 1.0f;
    if (r < 8)       src = Wq + r * 64 + s * 4;
    else if (r < 16) { src = Wk + (r - 8) * 64 + s * 4; scale = 1.44269504f; }
    else             src = Wv + (r - 16) * 64 + s * 4;
    float4 v = *(const float4*)src;
    __half h[4] = {__float2half_rn(v.x * scale), __float2half_rn(v.y * scale),
                   __float2half_rn(v.z * scale), __float2half_rn(v.w * scale)};
    *(uint2*)(g_wh + r * 64 + s * 4) = *(uint2*)h;
}

// ---------------------------------------------------------------------------
// Projection v4 (tensor cores, light CTAs): out[80,N] = g_wh[80,64] @ x[64,N].
// CTA = 32 n-cols, 4 warps (warp = 8-col strip), 512 CTAs.
// ---------------------------------------------------------------------------
__global__ __launch_bounds__(128) void proj_kernel(const float* __restrict__ x)
{
    __shared__ __half w_s[80][72];   // 11.5 KB (stride 144B: conflict-free)
    __shared__ __half x_s[64][40];   // 5 KB    (stride 80B: conflict-free)
    __shared__ __half o_s[80][40];   // 6.25 KB

    const int tid = threadIdx.x;
    const int lane = tid & 31, w = tid >> 5;
    const int g = lane >> 2, tc = lane & 3;
    const int gcol0 = blockIdx.x * PCOLS;
    const int b  = gcol0 >> 12;
    const int n0 = gcol0 & (NN - 1);

    // ---- weights via cp.async (fp16, pre-fused): 640 uint4 ----
    for (int i = tid; i < 640; i += 128) {
        int r = i >> 3, s = i & 7;
        cpa16(&w_s[r][s * 8], g_wh + r * 64 + s * 8);
    }
    cpa_commit();

    // ---- x tile [64 x 32] fp32 -> fp16 ----
    const float* xb = x + (size_t)b * CC * NN + n0;
#pragma unroll
    for (int i = 0; i < 4; i++) {
        int idx = tid + i * 128;                // 0..511
        int row = idx >> 3, s = idx & 7;
        float4 v = *(const float4*)(xb + (size_t)row * NN + s * 4);
        __half h[4] = {__float2half_rn(v.x), __float2half_rn(v.y),
                       __float2half_rn(v.z), __float2half_rn(v.w)};
        *(uint2*)&x_s[row][s * 4] = *(uint2*)h;
    }
    cpa_wait<0>();
    __syncthreads();

    // ---- MMA: warp w owns n-strip [w*8, w*8+8) ----
    const int nb = w * 8;
    float acc[5][4];
#pragma unroll
    for (int m = 0; m < 5; m++)
#pragma unroll
        for (int r = 0; r < 4; r++) acc[m][r] = 0.f;

#pragma unroll
    for (int k = 0; k < 4; k++) {
        unsigned b0, b1;
        ldm_x2_t(b0, b1, smem_u32(&x_s[k * 16 + (lane & 15)][nb]));
#pragma unroll
        for (int m = 0; m < 5; m++) {
            unsigned a0, a1, a2, a3;
            ldm_x4(a0, a1, a2, a3,
                   smem_u32(&w_s[m * 16 + (lane & 15)][k * 16 + 8 * (lane >> 4)]));
            mma_k16(acc[m], a0, a1, a2, a3, b0, b1);
        }
    }

    // ---- C fragments -> o_s (fp16) ----
#pragma unroll
    for (int m = 0; m < 5; m++) {
        int row = m * 16 + g, col = nb + tc * 2;
        o_s[row][col]         = __float2half_rn(acc[m][0]);
        o_s[row][col + 1]     = __float2half_rn(acc[m][1]);
        o_s[row + 8][col]     = __float2half_rn(acc[m][2]);
        o_s[row + 8][col + 1] = __float2half_rn(acc[m][3]);
    }
    __syncthreads();

    // ---- transpose-scatter: q (tid<32), k (tid 32..63) ----
    if (tid < 64) {
        int n = tid & 31;
        int rb = (tid < 32) ? 0 : 8;
        __half h[8];
#pragma unroll
        for (int r = 0; r < 8; r++) h[r] = o_s[rb + r][n];
        __half* dst = (tid < 32) ? g_qt : g_kt;
        *(uint4*)(dst + (size_t)(b * NN + n0 + n) * 8) = *(uint4*)h;
    }
    // ---- v + pad rows: g_vp[n][80], 10 uint4 per n-col ----
    for (int i = tid; i < PCOLS * 10; i += 128) {
        int n = i / 10, s = i % 10;
        __half h[8];
        if (s < 8) {
#pragma unroll
            for (int j = 0; j < 8; j++) h[j] = o_s[16 + s * 8 + j][n];
        } else if (s == 8) {
            h[0] = __float2half_rn(1.0f);                  // ones row (r=64)
#pragma unroll
            for (int j = 1; j < 8; j++) h[j] = __ushort_as_half(0);
        } else {
#pragma unroll
            for (int j = 0; j < 8; j++) h[j] = __ushort_as_half(0);
        }
        *(uint4*)(g_vp + (size_t)(b * NN + n0 + n) * MR + s * 8) = *(uint4*)h;
    }
}

// ---------------------------------------------------------------------------
// Attention main: CTA = (32 m-cols, batch, n-half). 4 warps, 1024 CTAs.
// S^T in fp16 accumulators (already log2-scaled via k weights) -> ex2 directly
// on the MMA C-fragments -> PV A-fragments. Triple-buffered cp.async,
// one __syncthreads per tile.
// ---------------------------------------------------------------------------
__global__ __launch_bounds__(128, 6) void attn_kernel()
{
    __shared__ __half k_s[BM][8];            // 0.5 KB
    __shared__ __half q_s[3][BN][8];         // 3 KB
    __shared__ __half v_s[3][BN][88];        // 33.8 KB (stride 176B: conflict-free)

    const int b  = blockIdx.y;
    const int m0 = blockIdx.x * BM;
    const int sp = blockIdx.z;
    const int s0 = sp * NHALF;
    const int tid = threadIdx.x;
    const int w = tid >> 5, lane = tid & 31, g = lane >> 2, tc = lane & 3;
    const int mt_ = w & 1;       // m-tile: cols mt_*16 .. +15
    const int rh  = w >> 1;      // r-half: rows rh*40 .. +39

    // ---- k tile ----
    if (tid < BM)
        *(uint4*)&k_s[tid][0] = *(const uint4*)(g_kt + (size_t)(b * NN + m0 + tid) * 8);

    // ---- prologue: prefetch tiles 0 and 1 ----
#pragma unroll
    for (int p = 0; p < 2; p++) {
        const int nn = s0 + p * BN;
        if (tid < BN)
            cpa16(&q_s[p][tid][0], g_qt + (size_t)(b * NN + nn + tid) * 8);
#pragma unroll
        for (int i = 0; i < 5; i++) {
            int e = tid + i * 128;
            int nl = e / 10, seg = e % 10;
            cpa16(&v_s[p][nl][seg * 8], g_vp + (size_t)(b * NN + nn + nl) * MR + seg * 8);
        }
        cpa_commit();
    }
    __syncthreads();   // k_s visible

    // A fragments for S^T (resident whole kernel)
    unsigned ka0, ka1;
    ldm_x2(ka0, ka1, smem_u32(&k_s[mt_ * 16 + (lane & 15)][0]));

    // O^T accumulators: m16 x (5 r8-tiles)
    float O[5][4];
#pragma unroll
    for (int rt = 0; rt < 5; rt++)
#pragma unroll
        for (int r = 0; r < 4; r++) O[rt][r] = 0.f;

    int cur = 0;

    for (int it = 0; it < NT; it++) {
        // ---- wait for tile it, fence all prior readers ----
        if (it == NT - 1) cpa_wait<0>(); else cpa_wait<1>();
        __syncthreads();

        // ---- issue prefetch of tile it+2 (buffer freed by the barrier) ----
        if (it + 2 < NT) {
            const int nxt = (cur + 2 >= 3) ? cur - 1 : cur + 2;
            const int nn = s0 + (it + 2) * BN;
            if (tid < BN)
                cpa16(&q_s[nxt][tid][0], g_qt + (size_t)(b * NN + nn + tid) * 8);
#pragma unroll
            for (int i = 0; i < 5; i++) {
                int e = tid + i * 128;
                int nl = e / 10, seg = e % 10;
                cpa16(&v_s[nxt][nl][seg * 8], g_vp + (size_t)(b * NN + nn + nl) * MR + seg * 8);
            }
            cpa_commit();
        }

        // ---- q B-fragments: 8 n8-tiles ----
        unsigned qb[8];
        ldm_x4(qb[0], qb[1], qb[2], qb[3], smem_u32(&q_s[cur][lane][0]));
        ldm_x4(qb[4], qb[5], qb[6], qb[7], smem_u32(&q_s[cur][32 + lane][0]));

        // ---- S^T (fp16 acc, log2 domain) -> ex2 -> PV A-fragments ----
        unsigned ea[4][4];
#pragma unroll
        for (int nt = 0; nt < 8; nt++) {
            unsigned c0 = 0, c1 = 0;
            mma_k8_f16(c0, c1, ka0, ka1, qb[nt]);
            unsigned e01, e23;
            asm volatile("ex2.approx.f16x2 %0, %1;\n" : "=r"(e01) : "r"(c0));
            asm volatile("ex2.approx.f16x2 %0, %1;\n" : "=r"(e23) : "r"(c1));
            ea[nt >> 1][(nt & 1) * 2]     = e01;
            ea[nt >> 1][(nt & 1) * 2 + 1] = e23;
        }

        // ---- O^T += E^T[m16, n64] @ V'^T[n64, r40] ----
#pragma unroll
        for (int ks = 0; ks < 4; ks++) {
            unsigned vb[10];
            ldm_x4_t(vb[0], vb[1], vb[2], vb[3],
                     smem_u32(&v_s[cur][ks * 16 + (lane & 15)][rh * 40 + 8 * (lane >> 4)]));
            ldm_x4_t(vb[4], vb[5], vb[6], vb[7],
                     smem_u32(&v_s[cur][ks * 16 + (lane & 15)][rh * 40 + 16 + 8 * (lane >> 4)]));
            ldm_x2_t(vb[8], vb[9],
                     smem_u32(&v_s[cur][ks * 16 + (lane & 15)][rh * 40 + 32]));
#pragma unroll
            for (int rt = 0; rt < 5; rt++)
                mma_k16(O[rt], ea[ks][0], ea[ks][1], ea[ks][2], ea[ks][3],
                        vb[2 * rt], vb[2 * rt + 1]);
        }

        cur = (cur + 1 == 3) ? 0 : cur + 1;
    }

    // ---- write fp32 partials (transposed): P[r][m] ----
    float* P = g_part + ((size_t)(sp * BB + b) * 65) * NN + m0;
    const int m = mt_ * 16 + g;
#pragma unroll
    for (int rt = 0; rt < 5; rt++) {
        int r = rh * 40 + rt * 8 + tc * 2;
        if (r < 64) {
            P[(size_t)r * NN + m]           = O[rt][0];
            P[(size_t)(r + 1) * NN + m]     = O[rt][1];
            P[(size_t)r * NN + m + 8]       = O[rt][2];
            P[(size_t)(r + 1) * NN + m + 8] = O[rt][3];
        } else if (r == 64) {   // denominator row
            P[(size_t)64 * NN + m]     = O[rt][0];
            P[(size_t)64 * NN + m + 8] = O[rt][2];
        }
    }
}

// ---------------------------------------------------------------------------
// Combine: out = gamma * (O0+O1)/(d0+d1) + x
// ---------------------------------------------------------------------------
__global__ __launch_bounds__(256) void combine_kernel(
    const float* __restrict__ x,
    const float* __restrict__ gamma,
    float* __restrict__ out)
{
    const int idx = blockIdx.x * 256 + threadIdx.x;
    const int e = idx * 4;
    const int b = e >> 18;
    const int c = (e >> 12) & 63;
    const int m = e & (NN - 1);

    const float* P0 = g_part + ((size_t)(0 * BB + b) * 65) * NN;
    const float* P1 = g_part + ((size_t)(1 * BB + b) * 65) * NN;

    float4 n0 = *(const float4*)(P0 + (size_t)c * NN + m);
    float4 n1 = *(const float4*)(P1 + (size_t)c * NN + m);
    float4 d0 = *(const float4*)(P0 + (size_t)64 * NN + m);
    float4 d1 = *(const float4*)(P1 + (size_t)64 * NN + m);
    float4 xv = *(const float4*)(x + (size_t)(b * CC + c) * NN + m);
    const float gam = *gamma;

    float4 o;
    o.x = gam * (n0.x + n1.x) / (d0.x + d1.x) + xv.x;
    o.y = gam * (n0.y + n1.y) / (d0.y + d1.y) + xv.y;
    o.z = gam * (n0.z + n1.z) / (d0.z + d1.z) + xv.z;
    o.w = gam * (n0.w + n1.w) / (d0.w + d1.w) + xv.w;
    *(float4*)(out + (size_t)(b * CC + c) * NN + m) = o;
}

// ---------------------------------------------------------------------------
extern "C" void kernel_launch(void* const* d_in, const int* in_sizes, int n_in,
                              void* d_out, int out_size)
{
    const float* x     = (const float*)d_in[0];
    const float* Wq    = (const float*)d_in[1];
    const float* Wk    = (const float*)d_in[2];
    const float* Wv    = (const float*)d_in[3];
    const float* gamma = (const float*)d_in[4];
    float* out = (float*)d_out;

    wconv_kernel<<<10, 128>>>(Wq, Wk, Wv);
    proj_kernel<<<(BB * NN) / PCOLS, 128>>>(x);
    attn_kernel<<<dim3(NN / BM, BB, NSPLIT), 128>>>();
    combine_kernel<<<(BB * CC * NN) / (256 * 4), 256>>>(x, gamma, out);
}